// round 2
// baseline (speedup 1.0000x reference)
#include <cuda_runtime.h>
#include <stdint.h>

#define NN 100000
#define NE 1600000
#define KD 256
#define FD 128   // HEADS*OUT_DIM
#define OD 32
#define NEG 0.2f

// Scratch (allocation-free rule: __device__ globals)
__device__ float g_feat[(size_t)NN * FD];   // 51.2 MB
__device__ float g_el[NN * 4];
__device__ float g_er[NN * 4];
__device__ float g_m[NN * 4];
__device__ float g_den[NN * 4];

__device__ __forceinline__ float lrelu(float v) { return v > 0.f ? v : NEG * v; }

__device__ __forceinline__ void atomicMaxFloat(float* addr, float val) {
    if (val >= 0.f)
        atomicMax((int*)addr, __float_as_int(val));
    else
        atomicMin((unsigned int*)addr, __float_as_uint(val));
}

// ---------------------------------------------------------------------------
// Init: zero output, set m = -inf, denom = 0
// ---------------------------------------------------------------------------
__global__ void k_init(float* __restrict__ out) {
    int i = blockIdx.x * 256 + threadIdx.x;
    if (i < NN * OD) out[i] = 0.f;
    if (i < NN * 4) {
        ((unsigned int*)g_m)[i] = 0xFF800000u;  // -inf
        g_den[i] = 0.f;
    }
}

// ---------------------------------------------------------------------------
// SGEMM: g_feat[M,128] = x[M,256] @ W[256,128]
// BM=128, BN=128, BK=8, TM=8, TN=8, 256 threads
// ---------------------------------------------------------------------------
__global__ __launch_bounds__(256) void k_gemm(const float* __restrict__ A,
                                              const float* __restrict__ B) {
    __shared__ float As[8][128];
    __shared__ float Bs[8][128];
    const int tid = threadIdx.x;
    const int bm = blockIdx.x * 128;
    const int arow = tid >> 1;          // 0..127
    const int acg  = (tid & 1) * 4;     // 0 or 4
    const int brow = tid >> 5;          // 0..7
    const int bcol = (tid & 31) * 4;    // 0..124
    const int ty = tid >> 4;            // 0..15 -> rows
    const int tx = tid & 15;            // 0..15 -> cols

    float acc[8][8];
#pragma unroll
    for (int i = 0; i < 8; i++)
#pragma unroll
        for (int j = 0; j < 8; j++) acc[i][j] = 0.f;

    int grow = bm + arow;
    if (grow >= NN) grow = NN - 1;      // clamp (stores are guarded)
    const float* Ap = A + (size_t)grow * KD + acg;

    for (int k0 = 0; k0 < KD; k0 += 8) {
        float4 av = *(const float4*)(Ap + k0);
        As[acg + 0][arow] = av.x;
        As[acg + 1][arow] = av.y;
        As[acg + 2][arow] = av.z;
        As[acg + 3][arow] = av.w;
        *(float4*)&Bs[brow][bcol] =
            *(const float4*)(B + (size_t)(k0 + brow) * FD + bcol);
        __syncthreads();
#pragma unroll
        for (int k = 0; k < 8; k++) {
            float4 a0 = *(const float4*)&As[k][ty * 8];
            float4 a1 = *(const float4*)&As[k][ty * 8 + 4];
            float4 b0 = *(const float4*)&Bs[k][tx * 8];
            float4 b1 = *(const float4*)&Bs[k][tx * 8 + 4];
            float a[8] = {a0.x, a0.y, a0.z, a0.w, a1.x, a1.y, a1.z, a1.w};
            float b[8] = {b0.x, b0.y, b0.z, b0.w, b1.x, b1.y, b1.z, b1.w};
#pragma unroll
            for (int i = 0; i < 8; i++)
#pragma unroll
                for (int j = 0; j < 8; j++) acc[i][j] += a[i] * b[j];
        }
        __syncthreads();
    }

#pragma unroll
    for (int i = 0; i < 8; i++) {
        int r = bm + ty * 8 + i;
        if (r < NN) {
            float* op = g_feat + (size_t)r * FD + tx * 8;
            *(float4*)op       = make_float4(acc[i][0], acc[i][1], acc[i][2], acc[i][3]);
            *(float4*)(op + 4) = make_float4(acc[i][4], acc[i][5], acc[i][6], acc[i][7]);
        }
    }
}

// ---------------------------------------------------------------------------
// el/er: per (node, head) dot products with attn_l / attn_r
// ---------------------------------------------------------------------------
__global__ void k_eler(const float* __restrict__ al, const float* __restrict__ ar) {
    int i = blockIdx.x * 256 + threadIdx.x;
    if (i >= NN * 4) return;
    int n = i >> 2, h = i & 3;
    const float4* f = (const float4*)(g_feat + (size_t)n * FD + h * OD);
    const float4* L = (const float4*)(al + h * OD);
    const float4* R = (const float4*)(ar + h * OD);
    float el = 0.f, er = 0.f;
#pragma unroll
    for (int j = 0; j < 8; j++) {
        float4 fv = __ldg(f + j);
        float4 lv = __ldg(L + j);
        float4 rv = __ldg(R + j);
        el += fv.x * lv.x + fv.y * lv.y + fv.z * lv.z + fv.w * lv.w;
        er += fv.x * rv.x + fv.y * rv.y + fv.z * rv.z + fv.w * rv.w;
    }
    g_el[i] = el;
    g_er[i] = er;
}

// ---------------------------------------------------------------------------
// Pass A: segment max of e over dst
// ---------------------------------------------------------------------------
__global__ void k_passA(const int* __restrict__ src, const int* __restrict__ dst) {
    int e = blockIdx.x * 256 + threadIdx.x;
    if (e >= NE) return;
    int s = src[e], d = dst[e];
    float4 el = __ldg((const float4*)(g_el + s * 4));
    float4 er = __ldg((const float4*)(g_er + d * 4));
    float* mp = g_m + d * 4;
    atomicMaxFloat(mp + 0, lrelu(el.x + er.x));
    atomicMaxFloat(mp + 1, lrelu(el.y + er.y));
    atomicMaxFloat(mp + 2, lrelu(el.z + er.z));
    atomicMaxFloat(mp + 3, lrelu(el.w + er.w));
}

// ---------------------------------------------------------------------------
// Pass B: denom = segment sum of exp(e - m)
// ---------------------------------------------------------------------------
__global__ void k_passB(const int* __restrict__ src, const int* __restrict__ dst) {
    int e = blockIdx.x * 256 + threadIdx.x;
    if (e >= NE) return;
    int s = src[e], d = dst[e];
    float4 el = __ldg((const float4*)(g_el + s * 4));
    float4 er = __ldg((const float4*)(g_er + d * 4));
    float4 m  = __ldg((const float4*)(g_m + d * 4));
    float* dp = g_den + d * 4;
    atomicAdd(dp + 0, __expf(lrelu(el.x + er.x) - m.x));
    atomicAdd(dp + 1, __expf(lrelu(el.y + er.y) - m.y));
    atomicAdd(dp + 2, __expf(lrelu(el.z + er.z) - m.z));
    atomicAdd(dp + 3, __expf(lrelu(el.w + er.w) - m.w));
}

// ---------------------------------------------------------------------------
// Pass C: out[dst] += sum_h a_h * feat[src,h,:] / 4   (head mean folded in)
// 8 threads per edge, each handles 4 output dims.
// ---------------------------------------------------------------------------
__global__ __launch_bounds__(256) void k_passC(const int* __restrict__ src,
                                               const int* __restrict__ dst,
                                               float* __restrict__ out) {
    int t = blockIdx.x * 256 + threadIdx.x;
    int e = t >> 3;
    int sub = t & 7;
    if (e >= NE) return;
    int s = src[e], d = dst[e];
    float4 el = __ldg((const float4*)(g_el + s * 4));
    float4 er = __ldg((const float4*)(g_er + d * 4));
    float4 m  = __ldg((const float4*)(g_m + d * 4));
    float4 dn = __ldg((const float4*)(g_den + d * 4));
    float a0 = __expf(lrelu(el.x + er.x) - m.x) / fmaxf(dn.x, 1e-9f) * 0.25f;
    float a1 = __expf(lrelu(el.y + er.y) - m.y) / fmaxf(dn.y, 1e-9f) * 0.25f;
    float a2 = __expf(lrelu(el.z + er.z) - m.z) / fmaxf(dn.z, 1e-9f) * 0.25f;
    float a3 = __expf(lrelu(el.w + er.w) - m.w) / fmaxf(dn.w, 1e-9f) * 0.25f;

    const float* fb = g_feat + (size_t)s * FD + sub * 4;
    float4 f0 = __ldg((const float4*)(fb + 0 * OD));
    float4 f1 = __ldg((const float4*)(fb + 1 * OD));
    float4 f2 = __ldg((const float4*)(fb + 2 * OD));
    float4 f3 = __ldg((const float4*)(fb + 3 * OD));

    float r0 = a0 * f0.x + a1 * f1.x + a2 * f2.x + a3 * f3.x;
    float r1 = a0 * f0.y + a1 * f1.y + a2 * f2.y + a3 * f3.y;
    float r2 = a0 * f0.z + a1 * f1.z + a2 * f2.z + a3 * f3.z;
    float r3 = a0 * f0.w + a1 * f1.w + a2 * f2.w + a3 * f3.w;

    float* op = out + (size_t)d * OD + sub * 4;
    asm volatile("red.global.add.v4.f32 [%0], {%1,%2,%3,%4};"
                 :: "l"(op), "f"(r0), "f"(r1), "f"(r2), "f"(r3)
                 : "memory");
}

// ---------------------------------------------------------------------------
extern "C" void kernel_launch(void* const* d_in, const int* in_sizes, int n_in,
                              void* d_out, int out_size) {
    const float* x  = (const float*)d_in[0];
    const float* W  = (const float*)d_in[1];
    const float* al = (const float*)d_in[2];
    const float* ar = (const float*)d_in[3];
    const int* src  = (const int*)d_in[4];
    const int* dst  = (const int*)d_in[5];
    float* out = (float*)d_out;

    k_init<<<(NN * OD + 255) / 256, 256>>>(out);
    k_gemm<<<(NN + 127) / 128, 256>>>(x, W);
    k_eler<<<(NN * 4 + 255) / 256, 256>>>(al, ar);
    k_passA<<<(NE + 255) / 256, 256>>>(src, dst);
    k_passB<<<(NE + 255) / 256, 256>>>(src, dst);
    k_passC<<<(NE * 8 + 255) / 256, 256>>>(src, dst, out);
}

// round 4
// speedup vs baseline: 1.5988x; 1.5988x over previous
#include <cuda_runtime.h>
#include <cuda_bf16.h>
#include <stdint.h>

#define NN 100000
#define NE 1600000
#define KD 256
#define FD 128   // HEADS*OUT_DIM
#define OD 32
#define NEG 0.2f

// Scratch (allocation-free rule: __device__ globals)
__device__ float g_feat[(size_t)NN * FD];   // 51.2 MB
__device__ float g_el[NN * 4];
__device__ float g_er[NN * 4];
__device__ float g_den[NN * 4];
__device__ __nv_bfloat16 g_Wt_hi[128 * 256];  // W^T split, [N=128][K=256]
__device__ __nv_bfloat16 g_Wt_lo[128 * 256];

__device__ __forceinline__ float lrelu(float v) { return v > 0.f ? v : NEG * v; }

// ---------------------------------------------------------------------------
// Init: zero output and denom
// ---------------------------------------------------------------------------
__global__ void k_init(float* __restrict__ out) {
    int i = blockIdx.x * 256 + threadIdx.x;
    if (i < NN * OD) out[i] = 0.f;
    if (i < NN * 4) g_den[i] = 0.f;
}

// ---------------------------------------------------------------------------
// Prep: transpose + bf16 hi/lo split of W [256,128] -> Wt [128,256]
// ---------------------------------------------------------------------------
__global__ void k_prep(const float* __restrict__ W) {
    int i = blockIdx.x * 256 + threadIdx.x;  // over 32768
    if (i >= 256 * 128) return;
    int k = i >> 7, n = i & 127;
    float w = W[i];
    __nv_bfloat16 h = __float2bfloat16_rn(w);
    float l = w - __bfloat162float(h);
    g_Wt_hi[n * 256 + k] = h;
    g_Wt_lo[n * 256 + k] = __float2bfloat16_rn(l);
}

// ---------------------------------------------------------------------------
// HMMA GEMM: g_feat = x @ W via mma.sync.m16n8k16 bf16, 3-term hi/lo split.
// Block: 128 threads (4 warps), 128x128 output tile; warp tile 64x64.
// smem: A_hi/A_lo [128 rows][40 halves-stride, 32 used], B likewise by N-row.
// ---------------------------------------------------------------------------
#define LDA 40  // padded stride in halves -> conflict-free frag loads

__device__ __forceinline__ void mma16816(float* c, const uint32_t* a, const uint32_t* b) {
    asm volatile(
        "mma.sync.aligned.m16n8k16.row.col.f32.bf16.bf16.f32 "
        "{%0,%1,%2,%3}, {%4,%5,%6,%7}, {%8,%9}, {%0,%1,%2,%3};"
        : "+f"(c[0]), "+f"(c[1]), "+f"(c[2]), "+f"(c[3])
        : "r"(a[0]), "r"(a[1]), "r"(a[2]), "r"(a[3]), "r"(b[0]), "r"(b[1]));
}

__global__ __launch_bounds__(128) void k_gemm_mma(const float* __restrict__ A) {
    __shared__ __align__(16) uint16_t sAhi[128 * LDA];
    __shared__ __align__(16) uint16_t sAlo[128 * LDA];
    __shared__ __align__(16) uint16_t sBhi[128 * LDA];
    __shared__ __align__(16) uint16_t sBlo[128 * LDA];

    const int tid = threadIdx.x;
    const int wid = tid >> 5, lid = tid & 31;
    const int g = lid >> 2, q = lid & 3;
    const int warp_m = (wid & 1) * 64, warp_n = (wid >> 1) * 64;
    const int bm = blockIdx.x * 128;

    float acc[4][8][4];
#pragma unroll
    for (int mt = 0; mt < 4; mt++)
#pragma unroll
        for (int nt = 0; nt < 8; nt++)
#pragma unroll
            for (int r = 0; r < 4; r++) acc[mt][nt][r] = 0.f;

    int grow = bm + tid;
    int crow = grow < NN ? grow : NN - 1;
    const float4* ap = (const float4*)(A + (size_t)crow * KD);

    for (int k0 = 0; k0 < KD; k0 += 32) {
        // ---- stage A chunk: thread tid = row tid, 32 fp32 -> hi/lo bf16 ----
        uint16_t* arow_h = sAhi + tid * LDA;
        uint16_t* arow_l = sAlo + tid * LDA;
#pragma unroll
        for (int j = 0; j < 8; j++) {
            float4 v = __ldg(ap + (k0 >> 2) + j);
            __nv_bfloat16 hx = __float2bfloat16_rn(v.x);
            __nv_bfloat16 hy = __float2bfloat16_rn(v.y);
            __nv_bfloat16 hz = __float2bfloat16_rn(v.z);
            __nv_bfloat16 hw = __float2bfloat16_rn(v.w);
            __nv_bfloat162 h0; h0.x = hx; h0.y = hy;
            __nv_bfloat162 h1; h1.x = hz; h1.y = hw;
            __nv_bfloat162 l0 = __floats2bfloat162_rn(v.x - __bfloat162float(hx),
                                                      v.y - __bfloat162float(hy));
            __nv_bfloat162 l1 = __floats2bfloat162_rn(v.z - __bfloat162float(hz),
                                                      v.w - __bfloat162float(hw));
            *(uint32_t*)(arow_h + j * 4)     = *(uint32_t*)&h0;
            *(uint32_t*)(arow_h + j * 4 + 2) = *(uint32_t*)&h1;
            *(uint32_t*)(arow_l + j * 4)     = *(uint32_t*)&l0;
            *(uint32_t*)(arow_l + j * 4 + 2) = *(uint32_t*)&l1;
        }
        // ---- stage B chunk: thread tid = n-row tid, 32 halves each ----
        {
            const uint4* bh = (const uint4*)(g_Wt_hi + tid * 256 + k0);
            const uint4* bl = (const uint4*)(g_Wt_lo + tid * 256 + k0);
            uint16_t* brow_h = sBhi + tid * LDA;
            uint16_t* brow_l = sBlo + tid * LDA;
#pragma unroll
            for (int j = 0; j < 4; j++) {
                *(uint4*)(brow_h + j * 8) = __ldg(bh + j);
                *(uint4*)(brow_l + j * 8) = __ldg(bl + j);
            }
        }
        __syncthreads();

        // ---- 3 terms x 2 ksteps of 16 ----
#pragma unroll
        for (int t = 0; t < 3; t++) {
            const uint16_t* As = (t == 2) ? sAlo : sAhi;
            const uint16_t* Bs = (t == 1) ? sBlo : sBhi;
#pragma unroll
            for (int kk = 0; kk < 32; kk += 16) {
                uint32_t af[4][4], bf[8][2];
#pragma unroll
                for (int mt = 0; mt < 4; mt++) {
                    const uint16_t* p = As + (warp_m + mt * 16 + g) * LDA + kk + q * 2;
                    af[mt][0] = *(const uint32_t*)(p);
                    af[mt][1] = *(const uint32_t*)(p + 8 * LDA);
                    af[mt][2] = *(const uint32_t*)(p + 8);
                    af[mt][3] = *(const uint32_t*)(p + 8 * LDA + 8);
                }
#pragma unroll
                for (int nt = 0; nt < 8; nt++) {
                    const uint16_t* p = Bs + (warp_n + nt * 8 + g) * LDA + kk + q * 2;
                    bf[nt][0] = *(const uint32_t*)(p);
                    bf[nt][1] = *(const uint32_t*)(p + 8);
                }
#pragma unroll
                for (int mt = 0; mt < 4; mt++)
#pragma unroll
                    for (int nt = 0; nt < 8; nt++)
                        mma16816(acc[mt][nt], af[mt], bf[nt]);
            }
        }
        __syncthreads();
    }

    // ---- store accumulators ----
#pragma unroll
    for (int mt = 0; mt < 4; mt++) {
        int r0 = bm + warp_m + mt * 16 + g;
        int r1 = r0 + 8;
#pragma unroll
        for (int nt = 0; nt < 8; nt++) {
            int col = warp_n + nt * 8 + q * 2;
            if (r0 < NN)
                *(float2*)(g_feat + (size_t)r0 * FD + col) =
                    make_float2(acc[mt][nt][0], acc[mt][nt][1]);
            if (r1 < NN)
                *(float2*)(g_feat + (size_t)r1 * FD + col) =
                    make_float2(acc[mt][nt][2], acc[mt][nt][3]);
        }
    }
}

// ---------------------------------------------------------------------------
// el/er: per (node, head) dot products with attn_l / attn_r
// ---------------------------------------------------------------------------
__global__ void k_eler(const float* __restrict__ al, const float* __restrict__ ar) {
    int i = blockIdx.x * 256 + threadIdx.x;
    if (i >= NN * 4) return;
    int n = i >> 2, h = i & 3;
    const float4* f = (const float4*)(g_feat + (size_t)n * FD + h * OD);
    const float4* L = (const float4*)(al + h * OD);
    const float4* R = (const float4*)(ar + h * OD);
    float el = 0.f, er = 0.f;
#pragma unroll
    for (int j = 0; j < 8; j++) {
        float4 fv = __ldg(f + j);
        float4 lv = __ldg(L + j);
        float4 rv = __ldg(R + j);
        el += fv.x * lv.x + fv.y * lv.y + fv.z * lv.z + fv.w * lv.w;
        er += fv.x * rv.x + fv.y * rv.y + fv.z * rv.z + fv.w * rv.w;
    }
    g_el[i] = el;
    g_er[i] = er;
}

// ---------------------------------------------------------------------------
// Pass B: denom = segment sum of exp(e)  (max-shift cancels algebraically)
// ---------------------------------------------------------------------------
__global__ void k_passB(const int* __restrict__ src, const int* __restrict__ dst) {
    int e = blockIdx.x * 256 + threadIdx.x;
    if (e >= NE) return;
    int s = src[e], d = dst[e];
    float4 el = __ldg((const float4*)(g_el + s * 4));
    float4 er = __ldg((const float4*)(g_er + d * 4));
    float r0 = __expf(lrelu(el.x + er.x));
    float r1 = __expf(lrelu(el.y + er.y));
    float r2 = __expf(lrelu(el.z + er.z));
    float r3 = __expf(lrelu(el.w + er.w));
    asm volatile("red.global.add.v4.f32 [%0], {%1,%2,%3,%4};"
                 :: "l"(g_den + d * 4), "f"(r0), "f"(r1), "f"(r2), "f"(r3)
                 : "memory");
}

// ---------------------------------------------------------------------------
// Pass C: out[dst] += sum_h a_h * feat[src,h,:] / 4   (head mean folded in)
// 8 threads per edge, each handles 4 output dims.
// ---------------------------------------------------------------------------
__global__ __launch_bounds__(256) void k_passC(const int* __restrict__ src,
                                               const int* __restrict__ dst,
                                               float* __restrict__ out) {
    int t = blockIdx.x * 256 + threadIdx.x;
    int e = t >> 3;
    int sub = t & 7;
    if (e >= NE) return;
    int s = src[e], d = dst[e];
    float4 el = __ldg((const float4*)(g_el + s * 4));
    float4 er = __ldg((const float4*)(g_er + d * 4));
    float4 dn = __ldg((const float4*)(g_den + d * 4));
    float a0 = __expf(lrelu(el.x + er.x)) / fmaxf(dn.x, 1e-9f) * 0.25f;
    float a1 = __expf(lrelu(el.y + er.y)) / fmaxf(dn.y, 1e-9f) * 0.25f;
    float a2 = __expf(lrelu(el.z + er.z)) / fmaxf(dn.z, 1e-9f) * 0.25f;
    float a3 = __expf(lrelu(el.w + er.w)) / fmaxf(dn.w, 1e-9f) * 0.25f;

    const float* fb = g_feat + (size_t)s * FD + sub * 4;
    float4 f0 = __ldg((const float4*)(fb + 0 * OD));
    float4 f1 = __ldg((const float4*)(fb + 1 * OD));
    float4 f2 = __ldg((const float4*)(fb + 2 * OD));
    float4 f3 = __ldg((const float4*)(fb + 3 * OD));

    float r0 = a0 * f0.x + a1 * f1.x + a2 * f2.x + a3 * f3.x;
    float r1 = a0 * f0.y + a1 * f1.y + a2 * f2.y + a3 * f3.y;
    float r2 = a0 * f0.z + a1 * f1.z + a2 * f2.z + a3 * f3.z;
    float r3 = a0 * f0.w + a1 * f1.w + a2 * f2.w + a3 * f3.w;

    float* op = out + (size_t)d * OD + sub * 4;
    asm volatile("red.global.add.v4.f32 [%0], {%1,%2,%3,%4};"
                 :: "l"(op), "f"(r0), "f"(r1), "f"(r2), "f"(r3)
                 : "memory");
}

// ---------------------------------------------------------------------------
extern "C" void kernel_launch(void* const* d_in, const int* in_sizes, int n_in,
                              void* d_out, int out_size) {
    const float* x  = (const float*)d_in[0];
    const float* W  = (const float*)d_in[1];
    const float* al = (const float*)d_in[2];
    const float* ar = (const float*)d_in[3];
    const int* src  = (const int*)d_in[4];
    const int* dst  = (const int*)d_in[5];
    float* out = (float*)d_out;

    k_init<<<(NN * OD + 255) / 256, 256>>>(out);
    k_prep<<<(256 * 128 + 255) / 256, 256>>>(W);
    k_gemm_mma<<<(NN + 127) / 128, 128>>>(x);
    k_eler<<<(NN * 4 + 255) / 256, 256>>>(al, ar);
    k_passB<<<(NE + 255) / 256, 256>>>(src, dst);
    k_passC<<<(NE * 8 + 255) / 256, 256>>>(src, dst, out);
}

// round 9
// speedup vs baseline: 1.7335x; 1.0843x over previous
#include <cuda_runtime.h>
#include <cuda_bf16.h>
#include <stdint.h>

#define NN 100000
#define NE 1600000
#define KD 256
#define FD 128   // HEADS*OUT_DIM
#define OD 32
#define NEG 0.2f

// Scratch (allocation-free rule: __device__ globals)
__device__ float g_feat[(size_t)NN * FD];   // 51.2 MB
__device__ float g_el[NN * 4];
__device__ float g_er[NN * 4];
__device__ float g_den[NN * 4];
__device__ __nv_bfloat16 g_Wt_hi[128 * 256];  // W^T split, [N=128][K=256]
__device__ __nv_bfloat16 g_Wt_lo[128 * 256];

__device__ __forceinline__ float lrelu(float v) { return v > 0.f ? v : NEG * v; }

// ---------------------------------------------------------------------------
// Init: zero output and denom
// ---------------------------------------------------------------------------
__global__ void k_init(float* __restrict__ out) {
    int i = blockIdx.x * 256 + threadIdx.x;
    if (i < NN * OD) out[i] = 0.f;
    if (i < NN * 4) g_den[i] = 0.f;
}

// ---------------------------------------------------------------------------
// Prep: transpose + bf16 hi/lo split of W [256,128] -> Wt [128,256]
// ---------------------------------------------------------------------------
__global__ void k_prep(const float* __restrict__ W) {
    int i = blockIdx.x * 256 + threadIdx.x;  // over 32768
    if (i >= 256 * 128) return;
    int k = i >> 7, n = i & 127;
    float w = W[i];
    __nv_bfloat16 h = __float2bfloat16_rn(w);
    float l = w - __bfloat162float(h);
    g_Wt_hi[n * 256 + k] = h;
    g_Wt_lo[n * 256 + k] = __float2bfloat16_rn(l);
}

// ---------------------------------------------------------------------------
// HMMA GEMM: g_feat = x @ W via mma.sync.m16n8k16 bf16, 3-term hi/lo split.
// Block: 128 threads (4 warps), 128x128 output tile; warp tile 64x64.
// Epilogue computes el/er from register-resident accumulators (fused; each
// warp's 64 n-cols = exactly 2 heads, so reduction stays in a 4-lane q-group).
// ---------------------------------------------------------------------------
#define LDA 40  // padded stride in halves -> conflict-free frag loads

__device__ __forceinline__ void mma16816(float* c, const uint32_t* a, const uint32_t* b) {
    asm volatile(
        "mma.sync.aligned.m16n8k16.row.col.f32.bf16.bf16.f32 "
        "{%0,%1,%2,%3}, {%4,%5,%6,%7}, {%8,%9}, {%0,%1,%2,%3};"
        : "+f"(c[0]), "+f"(c[1]), "+f"(c[2]), "+f"(c[3])
        : "r"(a[0]), "r"(a[1]), "r"(a[2]), "r"(a[3]), "r"(b[0]), "r"(b[1]));
}

__global__ __launch_bounds__(128) void k_gemm_mma(const float* __restrict__ A,
                                                  const float* __restrict__ al,
                                                  const float* __restrict__ ar) {
    __shared__ __align__(16) uint16_t sAhi[128 * LDA];
    __shared__ __align__(16) uint16_t sAlo[128 * LDA];
    __shared__ __align__(16) uint16_t sBhi[128 * LDA];
    __shared__ __align__(16) uint16_t sBlo[128 * LDA];
    __shared__ float sL[128];
    __shared__ float sR[128];

    const int tid = threadIdx.x;
    const int wid = tid >> 5, lid = tid & 31;
    const int g = lid >> 2, q = lid & 3;
    const int warp_m = (wid & 1) * 64, warp_n = (wid >> 1) * 64;
    const int bm = blockIdx.x * 128;

    if (tid < 32) ((float4*)sL)[tid] = __ldg((const float4*)al + tid);
    else if (tid < 64) ((float4*)sR)[tid - 32] = __ldg((const float4*)ar + (tid - 32));

    float acc[4][8][4];
#pragma unroll
    for (int mt = 0; mt < 4; mt++)
#pragma unroll
        for (int nt = 0; nt < 8; nt++)
#pragma unroll
            for (int r = 0; r < 4; r++) acc[mt][nt][r] = 0.f;

    int grow = bm + tid;
    int crow = grow < NN ? grow : NN - 1;
    const float4* ap = (const float4*)(A + (size_t)crow * KD);

    for (int k0 = 0; k0 < KD; k0 += 32) {
        // ---- stage A chunk: thread tid = row tid, 32 fp32 -> hi/lo bf16 ----
        uint16_t* arow_h = sAhi + tid * LDA;
        uint16_t* arow_l = sAlo + tid * LDA;
#pragma unroll
        for (int j = 0; j < 8; j++) {
            float4 v = __ldg(ap + (k0 >> 2) + j);
            __nv_bfloat16 hx = __float2bfloat16_rn(v.x);
            __nv_bfloat16 hy = __float2bfloat16_rn(v.y);
            __nv_bfloat16 hz = __float2bfloat16_rn(v.z);
            __nv_bfloat16 hw = __float2bfloat16_rn(v.w);
            __nv_bfloat162 h0; h0.x = hx; h0.y = hy;
            __nv_bfloat162 h1; h1.x = hz; h1.y = hw;
            __nv_bfloat162 l0 = __floats2bfloat162_rn(v.x - __bfloat162float(hx),
                                                      v.y - __bfloat162float(hy));
            __nv_bfloat162 l1 = __floats2bfloat162_rn(v.z - __bfloat162float(hz),
                                                      v.w - __bfloat162float(hw));
            *(uint32_t*)(arow_h + j * 4)     = *(uint32_t*)&h0;
            *(uint32_t*)(arow_h + j * 4 + 2) = *(uint32_t*)&h1;
            *(uint32_t*)(arow_l + j * 4)     = *(uint32_t*)&l0;
            *(uint32_t*)(arow_l + j * 4 + 2) = *(uint32_t*)&l1;
        }
        // ---- stage B chunk: thread tid = n-row tid, 32 halves each ----
        {
            const uint4* bh = (const uint4*)(g_Wt_hi + tid * 256 + k0);
            const uint4* bl = (const uint4*)(g_Wt_lo + tid * 256 + k0);
            uint16_t* brow_h = sBhi + tid * LDA;
            uint16_t* brow_l = sBlo + tid * LDA;
#pragma unroll
            for (int j = 0; j < 4; j++) {
                *(uint4*)(brow_h + j * 8) = __ldg(bh + j);
                *(uint4*)(brow_l + j * 8) = __ldg(bl + j);
            }
        }
        __syncthreads();

        // ---- 3 terms x 2 ksteps of 16 ----
#pragma unroll
        for (int t = 0; t < 3; t++) {
            const uint16_t* As = (t == 2) ? sAlo : sAhi;
            const uint16_t* Bs = (t == 1) ? sBlo : sBhi;
#pragma unroll
            for (int kk = 0; kk < 32; kk += 16) {
                uint32_t af[4][4], bf[8][2];
#pragma unroll
                for (int mt = 0; mt < 4; mt++) {
                    const uint16_t* p = As + (warp_m + mt * 16 + g) * LDA + kk + q * 2;
                    af[mt][0] = *(const uint32_t*)(p);
                    af[mt][1] = *(const uint32_t*)(p + 8 * LDA);
                    af[mt][2] = *(const uint32_t*)(p + 8);
                    af[mt][3] = *(const uint32_t*)(p + 8 * LDA + 8);
                }
#pragma unroll
                for (int nt = 0; nt < 8; nt++) {
                    const uint16_t* p = Bs + (warp_n + nt * 8 + g) * LDA + kk + q * 2;
                    bf[nt][0] = *(const uint32_t*)(p);
                    bf[nt][1] = *(const uint32_t*)(p + 8);
                }
#pragma unroll
                for (int mt = 0; mt < 4; mt++)
#pragma unroll
                    for (int nt = 0; nt < 8; nt++)
                        mma16816(acc[mt][nt], af[mt], bf[nt]);
            }
        }
        __syncthreads();
    }

    // ---- store accumulators + fused el/er ----
    const int hb = warp_n >> 5;  // head base: 0 (warp_n=0) or 2 (warp_n=64)
#pragma unroll
    for (int mt = 0; mt < 4; mt++) {
        int r0 = bm + warp_m + mt * 16 + g;
        int r1 = r0 + 8;
        // partial el/er: [row-half][head-within-warp]
        float pel[2][2] = {{0, 0}, {0, 0}};
        float per[2][2] = {{0, 0}, {0, 0}};
#pragma unroll
        for (int nt = 0; nt < 8; nt++) {
            int col = warp_n + nt * 8 + q * 2;
            int hh = nt >> 2;  // 0: first head of warp, 1: second
            float wl0 = sL[col], wl1 = sL[col + 1];
            float wr0 = sR[col], wr1 = sR[col + 1];
            pel[0][hh] += acc[mt][nt][0] * wl0 + acc[mt][nt][1] * wl1;
            per[0][hh] += acc[mt][nt][0] * wr0 + acc[mt][nt][1] * wr1;
            pel[1][hh] += acc[mt][nt][2] * wl0 + acc[mt][nt][3] * wl1;
            per[1][hh] += acc[mt][nt][2] * wr0 + acc[mt][nt][3] * wr1;

            if (r0 < NN)
                *(float2*)(g_feat + (size_t)r0 * FD + col) =
                    make_float2(acc[mt][nt][0], acc[mt][nt][1]);
            if (r1 < NN)
                *(float2*)(g_feat + (size_t)r1 * FD + col) =
                    make_float2(acc[mt][nt][2], acc[mt][nt][3]);
        }
        // reduce across the 4-lane q-group (lane bits 0..1)
#pragma unroll
        for (int half = 0; half < 2; half++)
#pragma unroll
            for (int hh = 0; hh < 2; hh++) {
                pel[half][hh] += __shfl_xor_sync(0xffffffffu, pel[half][hh], 1);
                pel[half][hh] += __shfl_xor_sync(0xffffffffu, pel[half][hh], 2);
                per[half][hh] += __shfl_xor_sync(0xffffffffu, per[half][hh], 1);
                per[half][hh] += __shfl_xor_sync(0xffffffffu, per[half][hh], 2);
            }
        if (q == 0) {
            if (r0 < NN) {
                *(float2*)(g_el + r0 * 4 + hb) = make_float2(pel[0][0], pel[0][1]);
                *(float2*)(g_er + r0 * 4 + hb) = make_float2(per[0][0], per[0][1]);
            }
            if (r1 < NN) {
                *(float2*)(g_el + r1 * 4 + hb) = make_float2(pel[1][0], pel[1][1]);
                *(float2*)(g_er + r1 * 4 + hb) = make_float2(per[1][0], per[1][1]);
            }
        }
    }
}

// ---------------------------------------------------------------------------
// Pass B: denom = segment sum of exp(e)  (max-shift cancels algebraically)
// ---------------------------------------------------------------------------
__global__ void k_passB(const int* __restrict__ src, const int* __restrict__ dst) {
    int e = blockIdx.x * 256 + threadIdx.x;
    if (e >= NE) return;
    int s = src[e], d = dst[e];
    float4 el = __ldg((const float4*)(g_el + s * 4));
    float4 er = __ldg((const float4*)(g_er + d * 4));
    float r0 = __expf(lrelu(el.x + er.x));
    float r1 = __expf(lrelu(el.y + er.y));
    float r2 = __expf(lrelu(el.z + er.z));
    float r3 = __expf(lrelu(el.w + er.w));
    asm volatile("red.global.add.v4.f32 [%0], {%1,%2,%3,%4};"
                 :: "l"(g_den + d * 4), "f"(r0), "f"(r1), "f"(r2), "f"(r3)
                 : "memory");
}

// ---------------------------------------------------------------------------
// Pass C: out[dst] += sum_h a_h * feat[src,h,:] / 4   (head mean folded in)
// 8 threads per edge, each handles 4 output dims.
// ---------------------------------------------------------------------------
__global__ __launch_bounds__(256) void k_passC(const int* __restrict__ src,
                                               const int* __restrict__ dst,
                                               float* __restrict__ out) {
    int t = blockIdx.x * 256 + threadIdx.x;
    int e = t >> 3;
    int sub = t & 7;
    if (e >= NE) return;
    int s = src[e], d = dst[e];
    float4 el = __ldg((const float4*)(g_el + s * 4));
    float4 er = __ldg((const float4*)(g_er + d * 4));
    float4 dn = __ldg((const float4*)(g_den + d * 4));
    float a0 = __expf(lrelu(el.x + er.x)) / fmaxf(dn.x, 1e-9f) * 0.25f;
    float a1 = __expf(lrelu(el.y + er.y)) / fmaxf(dn.y, 1e-9f) * 0.25f;
    float a2 = __expf(lrelu(el.z + er.z)) / fmaxf(dn.z, 1e-9f) * 0.25f;
    float a3 = __expf(lrelu(el.w + er.w)) / fmaxf(dn.w, 1e-9f) * 0.25f;

    const float* fb = g_feat + (size_t)s * FD + sub * 4;
    float4 f0 = __ldg((const float4*)(fb + 0 * OD));
    float4 f1 = __ldg((const float4*)(fb + 1 * OD));
    float4 f2 = __ldg((const float4*)(fb + 2 * OD));
    float4 f3 = __ldg((const float4*)(fb + 3 * OD));

    float r0 = a0 * f0.x + a1 * f1.x + a2 * f2.x + a3 * f3.x;
    float r1 = a0 * f0.y + a1 * f1.y + a2 * f2.y + a3 * f3.y;
    float r2 = a0 * f0.z + a1 * f1.z + a2 * f2.z + a3 * f3.z;
    float r3 = a0 * f0.w + a1 * f1.w + a2 * f2.w + a3 * f3.w;

    float* op = out + (size_t)d * OD + sub * 4;
    asm volatile("red.global.add.v4.f32 [%0], {%1,%2,%3,%4};"
                 :: "l"(op), "f"(r0), "f"(r1), "f"(r2), "f"(r3)
                 : "memory");
}

// ---------------------------------------------------------------------------
extern "C" void kernel_launch(void* const* d_in, const int* in_sizes, int n_in,
                              void* d_out, int out_size) {
    const float* x  = (const float*)d_in[0];
    const float* W  = (const float*)d_in[1];
    const float* al = (const float*)d_in[2];
    const float* ar = (const float*)d_in[3];
    const int* src  = (const int*)d_in[4];
    const int* dst  = (const int*)d_in[5];
    float* out = (float*)d_out;

    k_init<<<(NN * OD + 255) / 256, 256>>>(out);
    k_prep<<<(256 * 128 + 255) / 256, 256>>>(W);
    k_gemm_mma<<<(NN + 127) / 128, 128>>>(x, al, ar);
    k_passB<<<(NE + 255) / 256, 256>>>(src, dst);
    k_passC<<<(NE * 8 + 255) / 256, 256>>>(src, dst, out);
}

// round 11
// speedup vs baseline: 1.7607x; 1.0157x over previous
#include <cuda_runtime.h>
#include <cuda_bf16.h>
#include <cuda_fp16.h>
#include <stdint.h>

#define NN 100000
#define NE 1600000
#define KD 256
#define FD 128   // HEADS*OUT_DIM
#define OD 32
#define NEG 0.2f

// Scratch (allocation-free rule: __device__ globals)
__device__ __half g_feath[(size_t)NN * FD];  // 25.6 MB (fp16 feat, only consumer is passC)
__device__ float g_el[NN * 4];
__device__ float g_er[NN * 4];
__device__ float g_den[NN * 4];
__device__ __nv_bfloat16 g_Wt_hi[128 * 256];  // W^T split, [N=128][K=256]
__device__ __nv_bfloat16 g_Wt_lo[128 * 256];

__device__ __forceinline__ float lrelu(float v) { return v > 0.f ? v : NEG * v; }

// ---------------------------------------------------------------------------
// Init: zero output and denom
// ---------------------------------------------------------------------------
__global__ void k_init(float* __restrict__ out) {
    int i = blockIdx.x * 256 + threadIdx.x;
    if (i < NN * OD) out[i] = 0.f;
    if (i < NN * 4) g_den[i] = 0.f;
}

// ---------------------------------------------------------------------------
// Prep: transpose + bf16 hi/lo split of W [256,128] -> Wt [128,256]
// ---------------------------------------------------------------------------
__global__ void k_prep(const float* __restrict__ W) {
    int i = blockIdx.x * 256 + threadIdx.x;  // over 32768
    if (i >= 256 * 128) return;
    int k = i >> 7, n = i & 127;
    float w = W[i];
    __nv_bfloat16 h = __float2bfloat16_rn(w);
    float l = w - __bfloat162float(h);
    g_Wt_hi[n * 256 + k] = h;
    g_Wt_lo[n * 256 + k] = __float2bfloat16_rn(l);
}

// ---------------------------------------------------------------------------
// HMMA GEMM: feat = x @ W via mma.sync.m16n8k16 bf16, 3-term hi/lo split.
// Block: 128 threads (4 warps), 128x128 output tile; warp tile 64x64.
// Epilogue: fused el/er (register accumulators) + fp16 feat store.
// ---------------------------------------------------------------------------
#define LDA 40  // padded stride in halves -> conflict-free frag loads

__device__ __forceinline__ void mma16816(float* c, const uint32_t* a, const uint32_t* b) {
    asm volatile(
        "mma.sync.aligned.m16n8k16.row.col.f32.bf16.bf16.f32 "
        "{%0,%1,%2,%3}, {%4,%5,%6,%7}, {%8,%9}, {%0,%1,%2,%3};"
        : "+f"(c[0]), "+f"(c[1]), "+f"(c[2]), "+f"(c[3])
        : "r"(a[0]), "r"(a[1]), "r"(a[2]), "r"(a[3]), "r"(b[0]), "r"(b[1]));
}

__global__ __launch_bounds__(128) void k_gemm_mma(const float* __restrict__ A,
                                                  const float* __restrict__ al,
                                                  const float* __restrict__ ar) {
    __shared__ __align__(16) uint16_t sAhi[128 * LDA];
    __shared__ __align__(16) uint16_t sAlo[128 * LDA];
    __shared__ __align__(16) uint16_t sBhi[128 * LDA];
    __shared__ __align__(16) uint16_t sBlo[128 * LDA];
    __shared__ float sL[128];
    __shared__ float sR[128];

    const int tid = threadIdx.x;
    const int wid = tid >> 5, lid = tid & 31;
    const int g = lid >> 2, q = lid & 3;
    const int warp_m = (wid & 1) * 64, warp_n = (wid >> 1) * 64;
    const int bm = blockIdx.x * 128;

    if (tid < 32) ((float4*)sL)[tid] = __ldg((const float4*)al + tid);
    else if (tid < 64) ((float4*)sR)[tid - 32] = __ldg((const float4*)ar + (tid - 32));

    float acc[4][8][4];
#pragma unroll
    for (int mt = 0; mt < 4; mt++)
#pragma unroll
        for (int nt = 0; nt < 8; nt++)
#pragma unroll
            for (int r = 0; r < 4; r++) acc[mt][nt][r] = 0.f;

    int grow = bm + tid;
    int crow = grow < NN ? grow : NN - 1;
    const float4* ap = (const float4*)(A + (size_t)crow * KD);

    for (int k0 = 0; k0 < KD; k0 += 32) {
        // ---- stage A chunk: thread tid = row tid, 32 fp32 -> hi/lo bf16 ----
        uint16_t* arow_h = sAhi + tid * LDA;
        uint16_t* arow_l = sAlo + tid * LDA;
#pragma unroll
        for (int j = 0; j < 8; j++) {
            float4 v = __ldg(ap + (k0 >> 2) + j);
            __nv_bfloat16 hx = __float2bfloat16_rn(v.x);
            __nv_bfloat16 hy = __float2bfloat16_rn(v.y);
            __nv_bfloat16 hz = __float2bfloat16_rn(v.z);
            __nv_bfloat16 hw = __float2bfloat16_rn(v.w);
            __nv_bfloat162 h0; h0.x = hx; h0.y = hy;
            __nv_bfloat162 h1; h1.x = hz; h1.y = hw;
            __nv_bfloat162 l0 = __floats2bfloat162_rn(v.x - __bfloat162float(hx),
                                                      v.y - __bfloat162float(hy));
            __nv_bfloat162 l1 = __floats2bfloat162_rn(v.z - __bfloat162float(hz),
                                                      v.w - __bfloat162float(hw));
            *(uint32_t*)(arow_h + j * 4)     = *(uint32_t*)&h0;
            *(uint32_t*)(arow_h + j * 4 + 2) = *(uint32_t*)&h1;
            *(uint32_t*)(arow_l + j * 4)     = *(uint32_t*)&l0;
            *(uint32_t*)(arow_l + j * 4 + 2) = *(uint32_t*)&l1;
        }
        // ---- stage B chunk: thread tid = n-row tid, 32 halves each ----
        {
            const uint4* bh = (const uint4*)(g_Wt_hi + tid * 256 + k0);
            const uint4* bl = (const uint4*)(g_Wt_lo + tid * 256 + k0);
            uint16_t* brow_h = sBhi + tid * LDA;
            uint16_t* brow_l = sBlo + tid * LDA;
#pragma unroll
            for (int j = 0; j < 4; j++) {
                *(uint4*)(brow_h + j * 8) = __ldg(bh + j);
                *(uint4*)(brow_l + j * 8) = __ldg(bl + j);
            }
        }
        __syncthreads();

        // ---- 3 terms x 2 ksteps of 16 ----
#pragma unroll
        for (int t = 0; t < 3; t++) {
            const uint16_t* As = (t == 2) ? sAlo : sAhi;
            const uint16_t* Bs = (t == 1) ? sBlo : sBhi;
#pragma unroll
            for (int kk = 0; kk < 32; kk += 16) {
                uint32_t af[4][4], bf[8][2];
#pragma unroll
                for (int mt = 0; mt < 4; mt++) {
                    const uint16_t* p = As + (warp_m + mt * 16 + g) * LDA + kk + q * 2;
                    af[mt][0] = *(const uint32_t*)(p);
                    af[mt][1] = *(const uint32_t*)(p + 8 * LDA);
                    af[mt][2] = *(const uint32_t*)(p + 8);
                    af[mt][3] = *(const uint32_t*)(p + 8 * LDA + 8);
                }
#pragma unroll
                for (int nt = 0; nt < 8; nt++) {
                    const uint16_t* p = Bs + (warp_n + nt * 8 + g) * LDA + kk + q * 2;
                    bf[nt][0] = *(const uint32_t*)(p);
                    bf[nt][1] = *(const uint32_t*)(p + 8);
                }
#pragma unroll
                for (int mt = 0; mt < 4; mt++)
#pragma unroll
                    for (int nt = 0; nt < 8; nt++)
                        mma16816(acc[mt][nt], af[mt], bf[nt]);
            }
        }
        __syncthreads();
    }

    // ---- store fp16 accumulators + fused el/er ----
    const int hb = warp_n >> 5;  // head base: 0 (warp_n=0) or 2 (warp_n=64)
#pragma unroll
    for (int mt = 0; mt < 4; mt++) {
        int r0 = bm + warp_m + mt * 16 + g;
        int r1 = r0 + 8;
        float pel[2][2] = {{0, 0}, {0, 0}};
        float per[2][2] = {{0, 0}, {0, 0}};
#pragma unroll
        for (int nt = 0; nt < 8; nt++) {
            int col = warp_n + nt * 8 + q * 2;
            int hh = nt >> 2;
            float wl0 = sL[col], wl1 = sL[col + 1];
            float wr0 = sR[col], wr1 = sR[col + 1];
            pel[0][hh] += acc[mt][nt][0] * wl0 + acc[mt][nt][1] * wl1;
            per[0][hh] += acc[mt][nt][0] * wr0 + acc[mt][nt][1] * wr1;
            pel[1][hh] += acc[mt][nt][2] * wl0 + acc[mt][nt][3] * wl1;
            per[1][hh] += acc[mt][nt][2] * wr0 + acc[mt][nt][3] * wr1;

            if (r0 < NN) {
                __half2 h2 = __floats2half2_rn(acc[mt][nt][0], acc[mt][nt][1]);
                *(__half2*)(g_feath + (size_t)r0 * FD + col) = h2;
            }
            if (r1 < NN) {
                __half2 h2 = __floats2half2_rn(acc[mt][nt][2], acc[mt][nt][3]);
                *(__half2*)(g_feath + (size_t)r1 * FD + col) = h2;
            }
        }
        // reduce across the 4-lane q-group (lane bits 0..1)
#pragma unroll
        for (int half = 0; half < 2; half++)
#pragma unroll
            for (int hh = 0; hh < 2; hh++) {
                pel[half][hh] += __shfl_xor_sync(0xffffffffu, pel[half][hh], 1);
                pel[half][hh] += __shfl_xor_sync(0xffffffffu, pel[half][hh], 2);
                per[half][hh] += __shfl_xor_sync(0xffffffffu, per[half][hh], 1);
                per[half][hh] += __shfl_xor_sync(0xffffffffu, per[half][hh], 2);
            }
        if (q == 0) {
            if (r0 < NN) {
                *(float2*)(g_el + r0 * 4 + hb) = make_float2(pel[0][0], pel[0][1]);
                *(float2*)(g_er + r0 * 4 + hb) = make_float2(per[0][0], per[0][1]);
            }
            if (r1 < NN) {
                *(float2*)(g_el + r1 * 4 + hb) = make_float2(pel[1][0], pel[1][1]);
                *(float2*)(g_er + r1 * 4 + hb) = make_float2(per[1][0], per[1][1]);
            }
        }
    }
}

// ---------------------------------------------------------------------------
// Pass B: denom = segment sum of exp(e)  (max-shift cancels algebraically)
// ---------------------------------------------------------------------------
__global__ void k_passB(const int* __restrict__ src, const int* __restrict__ dst) {
    int e = blockIdx.x * 256 + threadIdx.x;
    if (e >= NE) return;
    int s = src[e], d = dst[e];
    float4 el = __ldg((const float4*)(g_el + s * 4));
    float4 er = __ldg((const float4*)(g_er + d * 4));
    float r0 = __expf(lrelu(el.x + er.x));
    float r1 = __expf(lrelu(el.y + er.y));
    float r2 = __expf(lrelu(el.z + er.z));
    float r3 = __expf(lrelu(el.w + er.w));
    asm volatile("red.global.add.v4.f32 [%0], {%1,%2,%3,%4};"
                 :: "l"(g_den + d * 4), "f"(r0), "f"(r1), "f"(r2), "f"(r3)
                 : "memory");
}

// ---------------------------------------------------------------------------
// Pass C: out[dst] += sum_h a_h * feat16[src,h,:] / 4   (head mean folded in)
// 8 threads per edge, thread sub handles out dims [sub*4, sub*4+4).
// feat is fp16: 4x 8B gather per thread (vs 4x 16B in fp32) -> halved L2 traffic.
// ---------------------------------------------------------------------------
__global__ __launch_bounds__(256) void k_passC(const int* __restrict__ src,
                                               const int* __restrict__ dst,
                                               float* __restrict__ out) {
    int t = blockIdx.x * 256 + threadIdx.x;
    int e = t >> 3;
    int sub = t & 7;
    if (e >= NE) return;
    int s = src[e], d = dst[e];
    float4 el = __ldg((const float4*)(g_el + s * 4));
    float4 er = __ldg((const float4*)(g_er + d * 4));
    float4 dn = __ldg((const float4*)(g_den + d * 4));
    float a0 = __expf(lrelu(el.x + er.x)) / fmaxf(dn.x, 1e-9f) * 0.25f;
    float a1 = __expf(lrelu(el.y + er.y)) / fmaxf(dn.y, 1e-9f) * 0.25f;
    float a2 = __expf(lrelu(el.z + er.z)) / fmaxf(dn.z, 1e-9f) * 0.25f;
    float a3 = __expf(lrelu(el.w + er.w)) / fmaxf(dn.w, 1e-9f) * 0.25f;

    const __half* fb = g_feath + (size_t)s * FD + sub * 4;
    __half2 f0a = __ldg((const __half2*)(fb + 0 * OD));
    __half2 f0b = __ldg((const __half2*)(fb + 0 * OD + 2));
    __half2 f1a = __ldg((const __half2*)(fb + 1 * OD));
    __half2 f1b = __ldg((const __half2*)(fb + 1 * OD + 2));
    __half2 f2a = __ldg((const __half2*)(fb + 2 * OD));
    __half2 f2b = __ldg((const __half2*)(fb + 2 * OD + 2));
    __half2 f3a = __ldg((const __half2*)(fb + 3 * OD));
    __half2 f3b = __ldg((const __half2*)(fb + 3 * OD + 2));

    float2 v0a = __half22float2(f0a), v0b = __half22float2(f0b);
    float2 v1a = __half22float2(f1a), v1b = __half22float2(f1b);
    float2 v2a = __half22float2(f2a), v2b = __half22float2(f2b);
    float2 v3a = __half22float2(f3a), v3b = __half22float2(f3b);

    float r0 = a0 * v0a.x + a1 * v1a.x + a2 * v2a.x + a3 * v3a.x;
    float r1 = a0 * v0a.y + a1 * v1a.y + a2 * v2a.y + a3 * v3a.y;
    float r2 = a0 * v0b.x + a1 * v1b.x + a2 * v2b.x + a3 * v3b.x;
    float r3 = a0 * v0b.y + a1 * v1b.y + a2 * v2b.y + a3 * v3b.y;

    float* op = out + (size_t)d * OD + sub * 4;
    asm volatile("red.global.add.v4.f32 [%0], {%1,%2,%3,%4};"
                 :: "l"(op), "f"(r0), "f"(r1), "f"(r2), "f"(r3)
                 : "memory");
}

// ---------------------------------------------------------------------------
extern "C" void kernel_launch(void* const* d_in, const int* in_sizes, int n_in,
                              void* d_out, int out_size) {
    const float* x  = (const float*)d_in[0];
    const float* W  = (const float*)d_in[1];
    const float* al = (const float*)d_in[2];
    const float* ar = (const float*)d_in[3];
    const int* src  = (const int*)d_in[4];
    const int* dst  = (const int*)d_in[5];
    float* out = (float*)d_out;

    k_init<<<(NN * OD + 255) / 256, 256>>>(out);
    k_prep<<<(256 * 128 + 255) / 256, 256>>>(W);
    k_gemm_mma<<<(NN + 127) / 128, 128>>>(x, al, ar);
    k_passB<<<(NE + 255) / 256, 256>>>(src, dst);
    k_passC<<<(NE * 8 + 255) / 256, 256>>>(src, dst, out);
}